// round 1
// baseline (speedup 1.0000x reference)
#include <cuda_runtime.h>
#include <math.h>

// Problem constants (fixed by setup_inputs)
#define BATCH 4
#define SEQ   2048
#define DIM   1024
#define HEADS 16
#define HDIM  64
#define MROWS (BATCH*SEQ)          // 8192

// Scratch (no cudaMalloc allowed)
__device__ float g_q[BATCH*HEADS*SEQ*HDIM];       // [b*H+h][s][hd]
__device__ float g_k[BATCH*HEADS*SEQ*HDIM];
__device__ float g_v[BATCH*HEADS*SEQ*HDIM];
__device__ float g_heads[MROWS*DIM];              // [b*S+s][D]

// ---------------------------------------------------------------------------
// Fused QKV projection GEMM: out = x @ W + b, 64x64 tile, 4x4 micro-tile.
// blockIdx.x : row tile (M/64 = 128)
// blockIdx.y : 0..47 -> which matrix (y/16) and head/col-tile (y%16)
// Writes into [b*H+h][s][hd] layout (col tile == head since HDIM==64).
// ---------------------------------------------------------------------------
__global__ __launch_bounds__(256) void qkv_kernel(
    const float* __restrict__ x,
    const float* __restrict__ Wq, const float* __restrict__ bq,
    const float* __restrict__ Wk, const float* __restrict__ bk,
    const float* __restrict__ Wv, const float* __restrict__ bv)
{
    __shared__ float As[16][68];   // [k][row], padded
    __shared__ float Bs[16][64];   // [k][col]

    const int mtile = blockIdx.x;
    const int ytile = blockIdx.y;
    const int which = ytile >> 4;     // 0=Q 1=K 2=V
    const int cb    = ytile & 15;     // head index / col tile

    const float* W    = (which == 0) ? Wq : (which == 1) ? Wk : Wv;
    const float* bias = (which == 0) ? bq : (which == 1) ? bk : bv;
    float*       out  = (which == 0) ? g_q : (which == 1) ? g_k : g_v;

    const int t  = threadIdx.x;
    const int tx = t & 15;
    const int ty = t >> 4;

    const int row0 = mtile * 64;
    const int col0 = cb * 64;

    // A tile load mapping: thread -> one float4 of x
    const int lr = t >> 2;          // 0..63 row
    const int lk = (t & 3) * 4;     // 0,4,8,12 within k-tile

    float acc[4][4];
    #pragma unroll
    for (int i = 0; i < 4; i++)
        #pragma unroll
        for (int j = 0; j < 4; j++) acc[i][j] = 0.f;

    for (int k0 = 0; k0 < DIM; k0 += 16) {
        float4 a = *(const float4*)&x[(row0 + lr) * DIM + k0 + lk];
        As[lk + 0][lr] = a.x;
        As[lk + 1][lr] = a.y;
        As[lk + 2][lr] = a.z;
        As[lk + 3][lr] = a.w;
        *(float4*)&Bs[ty][tx * 4] =
            *(const float4*)&W[(k0 + ty) * DIM + col0 + tx * 4];
        __syncthreads();
        #pragma unroll
        for (int kk = 0; kk < 16; kk++) {
            float4 av = *(float4*)&As[kk][ty * 4];
            float4 bv4 = *(float4*)&Bs[kk][tx * 4];
            float ar[4] = {av.x, av.y, av.z, av.w};
            float br[4] = {bv4.x, bv4.y, bv4.z, bv4.w};
            #pragma unroll
            for (int i = 0; i < 4; i++)
                #pragma unroll
                for (int j = 0; j < 4; j++)
                    acc[i][j] = fmaf(ar[i], br[j], acc[i][j]);
        }
        __syncthreads();
    }

    float4 bvec = *(const float4*)&bias[col0 + tx * 4];
    float br[4] = {bvec.x, bvec.y, bvec.z, bvec.w};

    #pragma unroll
    for (int i = 0; i < 4; i++) {
        int row = row0 + ty * 4 + i;
        int b = row >> 11;        // /2048
        int s = row & 2047;
        float4 v;
        v.x = acc[i][0] + br[0];
        v.y = acc[i][1] + br[1];
        v.z = acc[i][2] + br[2];
        v.w = acc[i][3] + br[3];
        *(float4*)&out[(((b * HEADS + cb) * SEQ) + s) * HDIM + tx * 4] = v;
    }
}

// ---------------------------------------------------------------------------
// Flash attention: per (q-tile of 64, head) block. Online softmax over 32
// key tiles of 64. Two 64x64x64 smem GEMMs per tile.
// ---------------------------------------------------------------------------
__global__ __launch_bounds__(256) void attn_kernel()
{
    extern __shared__ float sm[];
    float* Qs = sm;                 // [hd][qr]  64x68 (transposed, pre-scaled)
    float* Ks = Qs + 64 * 68;       // [hd][kr]  64x68 (transposed)
    float* Vs = Ks + 64 * 68;       // [kr][hd]  64x68
    float* Ps = Vs + 64 * 68;       // [kr][qr]  64x68

    const int qt = blockIdx.x;      // 0..31
    const int bh = blockIdx.y;      // 0..63
    const float* Q = g_q + (size_t)bh * SEQ * HDIM;
    const float* K = g_k + (size_t)bh * SEQ * HDIM;
    const float* V = g_v + (size_t)bh * SEQ * HDIM;

    const int t  = threadIdx.x;
    const int tx = t & 15;
    const int ty = t >> 4;

    // load Q tile transposed & pre-scaled by 1/sqrt(64)
    #pragma unroll
    for (int it = 0; it < 4; it++) {
        int fid = t + it * 256;          // 0..1023 float4 id
        int qr  = fid >> 4;
        int h4  = (fid & 15) * 4;
        float4 a = *(const float4*)&Q[(qt * 64 + qr) * HDIM + h4];
        Qs[(h4 + 0) * 68 + qr] = a.x * 0.125f;
        Qs[(h4 + 1) * 68 + qr] = a.y * 0.125f;
        Qs[(h4 + 2) * 68 + qr] = a.z * 0.125f;
        Qs[(h4 + 3) * 68 + qr] = a.w * 0.125f;
    }

    float o[4][4];
    float m[4], l[4];
    #pragma unroll
    for (int i = 0; i < 4; i++) {
        m[i] = -1e30f; l[i] = 0.f;
        #pragma unroll
        for (int j = 0; j < 4; j++) o[i][j] = 0.f;
    }

    for (int kt = 0; kt < SEQ / 64; kt++) {
        __syncthreads();   // prior reads of Ks/Vs/Qs done
        #pragma unroll
        for (int it = 0; it < 4; it++) {
            int fid = t + it * 256;
            int kr  = fid >> 4;
            int h4  = (fid & 15) * 4;
            float4 a = *(const float4*)&K[(kt * 64 + kr) * HDIM + h4];
            Ks[(h4 + 0) * 68 + kr] = a.x;
            Ks[(h4 + 1) * 68 + kr] = a.y;
            Ks[(h4 + 2) * 68 + kr] = a.z;
            Ks[(h4 + 3) * 68 + kr] = a.w;
            float4 vv = *(const float4*)&V[(kt * 64 + kr) * HDIM + h4];
            *(float4*)&Vs[kr * 68 + h4] = vv;
        }
        __syncthreads();

        // scores S = (Q*scale) @ K^T : 64x64
        float s[4][4];
        #pragma unroll
        for (int i = 0; i < 4; i++)
            #pragma unroll
            for (int j = 0; j < 4; j++) s[i][j] = 0.f;

        #pragma unroll 8
        for (int kk = 0; kk < 64; kk++) {
            float4 av  = *(float4*)&Qs[kk * 68 + 4 * ty];
            float4 bv4 = *(float4*)&Ks[kk * 68 + 4 * tx];
            float ar[4] = {av.x, av.y, av.z, av.w};
            float br[4] = {bv4.x, bv4.y, bv4.z, bv4.w};
            #pragma unroll
            for (int i = 0; i < 4; i++)
                #pragma unroll
                for (int j = 0; j < 4; j++)
                    s[i][j] = fmaf(ar[i], br[j], s[i][j]);
        }

        // online softmax update
        float p[4][4];
        #pragma unroll
        for (int i = 0; i < 4; i++) {
            float rm = fmaxf(fmaxf(s[i][0], s[i][1]), fmaxf(s[i][2], s[i][3]));
            #pragma unroll
            for (int off = 8; off >= 1; off >>= 1)
                rm = fmaxf(rm, __shfl_xor_sync(0xffffffffu, rm, off));
            float mn = fmaxf(m[i], rm);
            float f  = __expf(m[i] - mn);
            float rs = 0.f;
            #pragma unroll
            for (int j = 0; j < 4; j++) {
                p[i][j] = __expf(s[i][j] - mn);
                rs += p[i][j];
            }
            #pragma unroll
            for (int off = 8; off >= 1; off >>= 1)
                rs += __shfl_xor_sync(0xffffffffu, rs, off);
            l[i] = l[i] * f + rs;
            m[i] = mn;
            #pragma unroll
            for (int j = 0; j < 4; j++) o[i][j] *= f;
        }

        // store P transposed: Ps[k][qr]
        #pragma unroll
        for (int j = 0; j < 4; j++) {
            float4 col;
            col.x = p[0][j]; col.y = p[1][j]; col.z = p[2][j]; col.w = p[3][j];
            *(float4*)&Ps[(4 * tx + j) * 68 + 4 * ty] = col;
        }
        __syncthreads();

        // O += P @ V
        #pragma unroll 8
        for (int kk = 0; kk < 64; kk++) {
            float4 av  = *(float4*)&Ps[kk * 68 + 4 * ty];
            float4 bv4 = *(float4*)&Vs[kk * 68 + 4 * tx];
            float ar[4] = {av.x, av.y, av.z, av.w};
            float br[4] = {bv4.x, bv4.y, bv4.z, bv4.w};
            #pragma unroll
            for (int i = 0; i < 4; i++)
                #pragma unroll
                for (int j = 0; j < 4; j++)
                    o[i][j] = fmaf(ar[i], br[j], o[i][j]);
        }
    }

    // finalize & write heads[b*S+s][h*64+hd]
    const int b = bh >> 4, h = bh & 15;
    #pragma unroll
    for (int i = 0; i < 4; i++) {
        float inv = 1.f / l[i];
        int srow = qt * 64 + 4 * ty + i;
        float4 v;
        v.x = o[i][0] * inv;
        v.y = o[i][1] * inv;
        v.z = o[i][2] * inv;
        v.w = o[i][3] * inv;
        *(float4*)&g_heads[((size_t)(b * SEQ + srow)) * DIM + h * HDIM + 4 * tx] = v;
    }
}

// ---------------------------------------------------------------------------
// Output projection: out = heads @ Wo + bo
// ---------------------------------------------------------------------------
__global__ __launch_bounds__(256) void oproj_kernel(
    const float* __restrict__ Wo, const float* __restrict__ bo,
    float* __restrict__ out)
{
    __shared__ float As[16][68];
    __shared__ float Bs[16][64];

    const int mtile = blockIdx.x;   // 0..127
    const int cb    = blockIdx.y;   // 0..15

    const int t  = threadIdx.x;
    const int tx = t & 15;
    const int ty = t >> 4;

    const int row0 = mtile * 64;
    const int col0 = cb * 64;
    const int lr = t >> 2;
    const int lk = (t & 3) * 4;

    float acc[4][4];
    #pragma unroll
    for (int i = 0; i < 4; i++)
        #pragma unroll
        for (int j = 0; j < 4; j++) acc[i][j] = 0.f;

    for (int k0 = 0; k0 < DIM; k0 += 16) {
        float4 a = *(const float4*)&g_heads[(size_t)(row0 + lr) * DIM + k0 + lk];
        As[lk + 0][lr] = a.x;
        As[lk + 1][lr] = a.y;
        As[lk + 2][lr] = a.z;
        As[lk + 3][lr] = a.w;
        *(float4*)&Bs[ty][tx * 4] =
            *(const float4*)&Wo[(k0 + ty) * DIM + col0 + tx * 4];
        __syncthreads();
        #pragma unroll
        for (int kk = 0; kk < 16; kk++) {
            float4 av = *(float4*)&As[kk][ty * 4];
            float4 bv4 = *(float4*)&Bs[kk][tx * 4];
            float ar[4] = {av.x, av.y, av.z, av.w};
            float br[4] = {bv4.x, bv4.y, bv4.z, bv4.w};
            #pragma unroll
            for (int i = 0; i < 4; i++)
                #pragma unroll
                for (int j = 0; j < 4; j++)
                    acc[i][j] = fmaf(ar[i], br[j], acc[i][j]);
        }
        __syncthreads();
    }

    float4 bvec = *(const float4*)&bo[col0 + tx * 4];
    float br[4] = {bvec.x, bvec.y, bvec.z, bvec.w};

    #pragma unroll
    for (int i = 0; i < 4; i++) {
        int row = row0 + ty * 4 + i;
        float4 v;
        v.x = acc[i][0] + br[0];
        v.y = acc[i][1] + br[1];
        v.z = acc[i][2] + br[2];
        v.w = acc[i][3] + br[3];
        *(float4*)&out[(size_t)row * DIM + col0 + tx * 4] = v;
    }
}

extern "C" void kernel_launch(void* const* d_in, const int* in_sizes, int n_in,
                              void* d_out, int out_size)
{
    const float* x  = (const float*)d_in[0];
    const float* Wq = (const float*)d_in[1];
    const float* bq = (const float*)d_in[2];
    const float* Wk = (const float*)d_in[3];
    const float* bk = (const float*)d_in[4];
    const float* Wv = (const float*)d_in[5];
    const float* bv = (const float*)d_in[6];
    const float* Wo = (const float*)d_in[7];
    const float* bo = (const float*)d_in[8];
    float* out = (float*)d_out;

    static bool attr_set = false;
    if (!attr_set) {
        cudaFuncSetAttribute(attn_kernel,
                             cudaFuncAttributeMaxDynamicSharedMemorySize,
                             4 * 64 * 68 * (int)sizeof(float));
        attr_set = true;
    }

    qkv_kernel<<<dim3(MROWS / 64, 48), 256>>>(x, Wq, bq, Wk, bk, Wv, bv);
    attn_kernel<<<dim3(SEQ / 64, BATCH * HEADS), 256,
                  4 * 64 * 68 * sizeof(float)>>>();
    oproj_kernel<<<dim3(MROWS / 64, 16), 256>>>(Wo, bo, out);
}

// round 9
// speedup vs baseline: 1.6799x; 1.6799x over previous
#include <cuda_runtime.h>
#include <cuda_bf16.h>
#include <cstdint>
#include <math.h>

#define BATCH 4
#define SEQ   2048
#define DIM   1024
#define HEADS 16
#define HDIM  64
#define MROWS (BATCH*SEQ)

// Scratch (no cudaMalloc allowed) — referenced ONLY inside device code.
__device__ float g_q[BATCH*HEADS*SEQ*HDIM];
__device__ float g_k[BATCH*HEADS*SEQ*HDIM];
__device__ float g_v[BATCH*HEADS*SEQ*HDIM];
__device__ float g_heads[MROWS*DIM];
__device__ int   g_flags[4][1024];   // per-gemm, per-128x64-tile "mma ok" flag

// ---------------------------------------------------------------------------
// bf16 m16n8k16 mma
// ---------------------------------------------------------------------------
__device__ __forceinline__ void mma_bf16(float c[4], const unsigned a[4], const unsigned b[2]) {
    asm volatile(
        "mma.sync.aligned.m16n8k16.row.col.f32.bf16.bf16.f32 "
        "{%0,%1,%2,%3},{%4,%5,%6,%7},{%8,%9},{%0,%1,%2,%3};"
        : "+f"(c[0]), "+f"(c[1]), "+f"(c[2]), "+f"(c[3])
        : "r"(a[0]), "r"(a[1]), "r"(a[2]), "r"(a[3]), "r"(b[0]), "r"(b[1]));
}

__device__ __forceinline__ void split1(float x, unsigned short &h, unsigned short &l) {
    __nv_bfloat16 hb = __float2bfloat16(x);
    __nv_bfloat16 lb = __float2bfloat16(x - __bfloat162float(hb));
    h = *(const unsigned short*)&hb;
    l = *(const unsigned short*)&lb;
}

__device__ __forceinline__ void split_pack(float x0, float x1, unsigned &hw, unsigned &lw) {
    unsigned short h0, l0, h1, l1;
    split1(x0, h0, l0);
    split1(x1, h1, l1);
    hw = (unsigned)h0 | ((unsigned)h1 << 16);
    lw = (unsigned)l0 | ((unsigned)l1 << 16);
}

// ---------------------------------------------------------------------------
// Projection GEMM via split-bf16 mma: out = A @ W + bias. Block 128x64, K=32.
// 8 warps: 4 along M, 2 along N. gemm_id selects flag row; which selects the
// internal output buffer when HEADOUT.
// ---------------------------------------------------------------------------
template<bool HEADOUT>
__global__ __launch_bounds__(256) void proj_mma(
    const float* __restrict__ Ain, const float* __restrict__ W,
    const float* __restrict__ bias, float* __restrict__ outp,
    int which, int gemm_id)
{
    const float* A = Ain ? Ain : (const float*)g_heads;
    float* out = HEADOUT ? (which == 0 ? g_q : which == 1 ? g_k : g_v) : outp;

    __shared__ __align__(16) unsigned Ahw[128*20], Alw[128*20];
    __shared__ __align__(16) unsigned Bhw[64*20],  Blw[64*20];
    unsigned short* BhS = (unsigned short*)Bhw;
    unsigned short* BlS = (unsigned short*)Blw;

    const int t    = threadIdx.x;
    const int lane = t & 31;
    const int w    = t >> 5;
    const int g    = lane >> 2;
    const int tig  = lane & 3;
    const int wm   = w & 3;
    const int wn   = w >> 2;
    const int row0 = blockIdx.x * 128;
    const int col0 = blockIdx.y * 64;

    const int amr = t >> 3;
    const int akc = (t & 7) * 4;
    const int bkr = t >> 4;
    const int bnc = (t & 15) * 4;

    float c[2][4][4];
    #pragma unroll
    for (int mt = 0; mt < 2; mt++)
        #pragma unroll
        for (int nt = 0; nt < 4; nt++)
            #pragma unroll
            for (int i = 0; i < 4; i++) c[mt][nt][i] = 0.f;

    float4 pa[4], pb[2];
    #pragma unroll
    for (int it = 0; it < 4; it++)
        pa[it] = *(const float4*)&A[(size_t)(row0 + amr + 32*it) * DIM + akc];
    #pragma unroll
    for (int it = 0; it < 2; it++)
        pb[it] = *(const float4*)&W[(size_t)(bkr + 16*it) * DIM + col0 + bnc];

    for (int k0 = 0; k0 < DIM; k0 += 32) {
        #pragma unroll
        for (int it = 0; it < 4; it++) {
            float4 v = pa[it];
            unsigned h0, l0, h1, l1;
            split_pack(v.x, v.y, h0, l0);
            split_pack(v.z, v.w, h1, l1);
            const int wi = (amr + 32*it) * 20 + (akc >> 1);
            *(uint2*)&Ahw[wi] = make_uint2(h0, h1);
            *(uint2*)&Alw[wi] = make_uint2(l0, l1);
        }
        #pragma unroll
        for (int it = 0; it < 2; it++) {
            float4 v = pb[it];
            const int kr = bkr + 16*it;
            float vv[4] = {v.x, v.y, v.z, v.w};
            #pragma unroll
            for (int j = 0; j < 4; j++) {
                unsigned short h, l;
                split1(vv[j], h, l);
                BhS[(bnc + j) * 40 + kr] = h;
                BlS[(bnc + j) * 40 + kr] = l;
            }
        }
        __syncthreads();

        if (k0 + 32 < DIM) {
            #pragma unroll
            for (int it = 0; it < 4; it++)
                pa[it] = *(const float4*)&A[(size_t)(row0 + amr + 32*it) * DIM + k0 + 32 + akc];
            #pragma unroll
            for (int it = 0; it < 2; it++)
                pb[it] = *(const float4*)&W[(size_t)(bkr + 16*it + k0 + 32) * DIM + col0 + bnc];
        }

        #pragma unroll
        for (int c2 = 0; c2 < 2; c2++) {
            const int base = c2 * 8;
            unsigned ah[2][4], al[2][4], bh[4][2], bl[4][2];
            #pragma unroll
            for (int mt = 0; mt < 2; mt++) {
                const int rb = wm * 32 + mt * 16;
                ah[mt][0] = Ahw[(rb + g    ) * 20 + base + tig    ];
                ah[mt][1] = Ahw[(rb + g + 8) * 20 + base + tig    ];
                ah[mt][2] = Ahw[(rb + g    ) * 20 + base + tig + 4];
                ah[mt][3] = Ahw[(rb + g + 8) * 20 + base + tig + 4];
                al[mt][0] = Alw[(rb + g    ) * 20 + base + tig    ];
                al[mt][1] = Alw[(rb + g + 8) * 20 + base + tig    ];
                al[mt][2] = Alw[(rb + g    ) * 20 + base + tig + 4];
                al[mt][3] = Alw[(rb + g + 8) * 20 + base + tig + 4];
            }
            #pragma unroll
            for (int nt = 0; nt < 4; nt++) {
                const int n = wn * 32 + nt * 8 + g;
                bh[nt][0] = Bhw[n * 20 + base + tig    ];
                bh[nt][1] = Bhw[n * 20 + base + tig + 4];
                bl[nt][0] = Blw[n * 20 + base + tig    ];
                bl[nt][1] = Blw[n * 20 + base + tig + 4];
            }
            #pragma unroll
            for (int mt = 0; mt < 2; mt++)
                #pragma unroll
                for (int nt = 0; nt < 4; nt++) {
                    mma_bf16(c[mt][nt], ah[mt], bh[nt]);
                    mma_bf16(c[mt][nt], al[mt], bh[nt]);
                    mma_bf16(c[mt][nt], ah[mt], bl[nt]);
                }
        }
        __syncthreads();
    }

    // epilogue
    #pragma unroll
    for (int nt = 0; nt < 4; nt++) {
        const int cloc = wn * 32 + nt * 8 + 2 * tig;
        const int cc   = col0 + cloc;
        float2 bb = *(const float2*)&bias[cc];
        #pragma unroll
        for (int mt = 0; mt < 2; mt++) {
            #pragma unroll
            for (int hi = 0; hi < 2; hi++) {
                const int r = row0 + wm * 32 + mt * 16 + g + 8 * hi;
                float2 v;
                v.x = c[mt][nt][2*hi]     + bb.x;
                v.y = c[mt][nt][2*hi + 1] + bb.y;
                if (HEADOUT) {
                    const int b = r >> 11;
                    const int s = r & 2047;
                    *(float2*)&out[(((size_t)(b * HEADS + blockIdx.y) * SEQ) + s) * HDIM + cloc] = v;
                } else {
                    *(float2*)&out[(size_t)r * DIM + cc] = v;
                }
            }
        }
    }

    // oracle: warp 0 verifies row0, cols col0..col0+31 against fp32 gmem dot
    __threadfence_block();
    __syncthreads();
    if (w == 0) {
        const int col = col0 + lane;
        const float* ar = A + (size_t)row0 * DIM;
        const float* wc = W + col;
        float r0 = 0.f, r1 = 0.f, r2 = 0.f, r3 = 0.f;
        #pragma unroll 4
        for (int k = 0; k < DIM; k += 4) {
            r0 = fmaf(ar[k],     wc[(size_t)k * DIM],           r0);
            r1 = fmaf(ar[k + 1], wc[(size_t)(k + 1) * DIM],     r1);
            r2 = fmaf(ar[k + 2], wc[(size_t)(k + 2) * DIM],     r2);
            r3 = fmaf(ar[k + 3], wc[(size_t)(k + 3) * DIM],     r3);
        }
        float ref = (r0 + r1) + (r2 + r3) + bias[col];
        float got;
        if (HEADOUT) {
            const int b = row0 >> 11;
            const int s = row0 & 2047;
            got = out[(((size_t)(b * HEADS + blockIdx.y) * SEQ) + s) * HDIM + lane];
        } else {
            got = out[(size_t)row0 * DIM + col];
        }
        bool ok = fabsf(got - ref) <= (1e-2f + 2e-2f * fabsf(ref));
        unsigned msk = __ballot_sync(0xffffffffu, ok);
        if (lane == 0)
            g_flags[gemm_id][blockIdx.x * 16 + blockIdx.y] = (msk == 0xffffffffu) ? 1 : 0;
    }
}

// ---------------------------------------------------------------------------
// SIMT repair kernel (round-1 proven body): 64x64 tiles, grid (128,16).
// Runs only for tiles whose mma flag is 0.
// ---------------------------------------------------------------------------
template<bool HEADOUT>
__global__ __launch_bounds__(256) void proj_fix(
    const float* __restrict__ Ain, const float* __restrict__ W,
    const float* __restrict__ bias, float* __restrict__ outp,
    int which, int gemm_id)
{
    if (g_flags[gemm_id][(blockIdx.x >> 1) * 16 + blockIdx.y] != 0) return;

    const float* A = Ain ? Ain : (const float*)g_heads;
    float* out = HEADOUT ? (which == 0 ? g_q : which == 1 ? g_k : g_v) : outp;

    __shared__ float As[16][68];
    __shared__ float Bs[16][64];

    const int t  = threadIdx.x;
    const int tx = t & 15;
    const int ty = t >> 4;
    const int row0 = blockIdx.x * 64;
    const int col0 = blockIdx.y * 64;
    const int lr = t >> 2;
    const int lk = (t & 3) * 4;

    float acc[4][4];
    #pragma unroll
    for (int i = 0; i < 4; i++)
        #pragma unroll
        for (int j = 0; j < 4; j++) acc[i][j] = 0.f;

    for (int k0 = 0; k0 < DIM; k0 += 16) {
        float4 a = *(const float4*)&A[(size_t)(row0 + lr) * DIM + k0 + lk];
        As[lk + 0][lr] = a.x;
        As[lk + 1][lr] = a.y;
        As[lk + 2][lr] = a.z;
        As[lk + 3][lr] = a.w;
        *(float4*)&Bs[ty][tx * 4] =
            *(const float4*)&W[(size_t)(k0 + ty) * DIM + col0 + tx * 4];
        __syncthreads();
        #pragma unroll
        for (int kk = 0; kk < 16; kk++) {
            float4 av = *(float4*)&As[kk][ty * 4];
            float4 bv4 = *(float4*)&Bs[kk][tx * 4];
            float ar[4] = {av.x, av.y, av.z, av.w};
            float br[4] = {bv4.x, bv4.y, bv4.z, bv4.w};
            #pragma unroll
            for (int i = 0; i < 4; i++)
                #pragma unroll
                for (int j = 0; j < 4; j++)
                    acc[i][j] = fmaf(ar[i], br[j], acc[i][j]);
        }
        __syncthreads();
    }

    float4 bvec = *(const float4*)&bias[col0 + tx * 4];
    float br[4] = {bvec.x, bvec.y, bvec.z, bvec.w};

    #pragma unroll
    for (int i = 0; i < 4; i++) {
        int row = row0 + ty * 4 + i;
        float4 v;
        v.x = acc[i][0] + br[0];
        v.y = acc[i][1] + br[1];
        v.z = acc[i][2] + br[2];
        v.w = acc[i][3] + br[3];
        if (HEADOUT) {
            const int b = row >> 11;
            const int s = row & 2047;
            *(float4*)&out[(((size_t)(b * HEADS + blockIdx.y) * SEQ) + s) * HDIM + tx * 4] = v;
        } else {
            *(float4*)&out[(size_t)row * DIM + col0 + tx * 4] = v;
        }
    }
}

// ---------------------------------------------------------------------------
// Flash attention, split-bf16 mma. Block: 128 q x one (b,h). 8 warps (4Mx2N).
// ---------------------------------------------------------------------------
__global__ __launch_bounds__(256) void attn_mma()
{
    extern __shared__ __align__(16) unsigned smw[];
    unsigned* Qh = smw;
    unsigned* Ql = Qh + 128*36;
    unsigned* Kh = Ql + 128*36;
    unsigned* Kl = Kh + 64*36;
    unsigned* Vh = Kl + 64*36;       // [hd][key] transposed
    unsigned* Vl = Vh + 64*36;
    unsigned* Ph = Vl + 64*36;
    unsigned* Pl = Ph + 128*36;
    float* pmax = (float*)(Pl + 128*36);
    float* psum = pmax + 256;

    const int t    = threadIdx.x;
    const int lane = t & 31;
    const int w    = t >> 5;
    const int g    = lane >> 2;
    const int tig  = lane & 3;
    const int wm   = w & 3;
    const int wn   = w >> 2;
    const int qt   = blockIdx.x;
    const int bh   = blockIdx.y;

    const float* Q  = g_q + (size_t)bh * SEQ * HDIM;
    const float* Kp = g_k + (size_t)bh * SEQ * HDIM;
    const float* Vp = g_v + (size_t)bh * SEQ * HDIM;

    #pragma unroll
    for (int it = 0; it < 8; it++) {
        int fid = t + it * 256;
        int r = fid >> 4, c4 = (fid & 15) * 4;
        float4 v = *(const float4*)&Q[(size_t)(qt * 128 + r) * HDIM + c4];
        unsigned h0, l0, h1, l1;
        split_pack(v.x * 0.125f, v.y * 0.125f, h0, l0);
        split_pack(v.z * 0.125f, v.w * 0.125f, h1, l1);
        const int wi = r * 36 + (c4 >> 1);
        *(uint2*)&Qh[wi] = make_uint2(h0, h1);
        *(uint2*)&Ql[wi] = make_uint2(l0, l1);
    }

    float mst[2][2], lst[2][2], o[2][4][4];
    #pragma unroll
    for (int mt = 0; mt < 2; mt++)
        #pragma unroll
        for (int hi = 0; hi < 2; hi++) { mst[mt][hi] = -1e30f; lst[mt][hi] = 0.f; }
    #pragma unroll
    for (int mt = 0; mt < 2; mt++)
        #pragma unroll
        for (int nt = 0; nt < 4; nt++)
            #pragma unroll
            for (int i = 0; i < 4; i++) o[mt][nt][i] = 0.f;

    unsigned short* VhS = (unsigned short*)Vh;
    unsigned short* VlS = (unsigned short*)Vl;

    for (int kt = 0; kt < SEQ / 64; kt++) {
        __syncthreads();
        #pragma unroll
        for (int it = 0; it < 4; it++) {
            int fid = t + it * 256;
            int r = fid >> 4, c4 = (fid & 15) * 4;
            float4 kv = *(const float4*)&Kp[(size_t)(kt * 64 + r) * HDIM + c4];
            unsigned h0, l0, h1, l1;
            split_pack(kv.x, kv.y, h0, l0);
            split_pack(kv.z, kv.w, h1, l1);
            const int wi = r * 36 + (c4 >> 1);
            *(uint2*)&Kh[wi] = make_uint2(h0, h1);
            *(uint2*)&Kl[wi] = make_uint2(l0, l1);
            float4 vv = *(const float4*)&Vp[(size_t)(kt * 64 + r) * HDIM + c4];
            float va[4] = {vv.x, vv.y, vv.z, vv.w};
            #pragma unroll
            for (int j = 0; j < 4; j++) {
                unsigned short h, l;
                split1(va[j], h, l);
                VhS[(c4 + j) * 72 + r] = h;
                VlS[(c4 + j) * 72 + r] = l;
            }
        }
        __syncthreads();

        // S = Q @ K^T
        float s[2][4][4];
        #pragma unroll
        for (int mt = 0; mt < 2; mt++)
            #pragma unroll
            for (int nt = 0; nt < 4; nt++)
                #pragma unroll
                for (int i = 0; i < 4; i++) s[mt][nt][i] = 0.f;

        #pragma unroll
        for (int c2 = 0; c2 < 4; c2++) {
            const int base = c2 * 8;
            unsigned ah[2][4], al[2][4], bhf[4][2], blf[4][2];
            #pragma unroll
            for (int mt = 0; mt < 2; mt++) {
                const int rb = wm * 32 + mt * 16;
                ah[mt][0] = Qh[(rb + g    ) * 36 + base + tig    ];
                ah[mt][1] = Qh[(rb + g + 8) * 36 + base + tig    ];
                ah[mt][2] = Qh[(rb + g    ) * 36 + base + tig + 4];
                ah[mt][3] = Qh[(rb + g + 8) * 36 + base + tig + 4];
                al[mt][0] = Ql[(rb + g    ) * 36 + base + tig    ];
                al[mt][1] = Ql[(rb + g + 8) * 36 + base + tig    ];
                al[mt][2] = Ql[(rb + g    ) * 36 + base + tig + 4];
                al[mt][3] = Ql[(rb + g + 8) * 36 + base + tig + 4];
            }
            #pragma unroll
            for (int nt = 0; nt < 4; nt++) {
                const int n = wn * 32 + nt * 8 + g;
                bhf[nt][0] = Kh[n * 36 + base + tig    ];
                bhf[nt][1] = Kh[n * 36 + base + tig + 4];
                blf[nt][0] = Kl[n * 36 + base + tig    ];
                blf[nt][1] = Kl[n * 36 + base + tig + 4];
            }
            #pragma unroll
            for (int mt = 0; mt < 2; mt++)
                #pragma unroll
                for (int nt = 0; nt < 4; nt++) {
                    mma_bf16(s[mt][nt], ah[mt], bhf[nt]);
                    mma_bf16(s[mt][nt], al[mt], bhf[nt]);
                    mma_bf16(s[mt][nt], ah[mt], blf[nt]);
                }
        }

        // online softmax
        #pragma unroll
        for (int mt = 0; mt < 2; mt++)
            #pragma unroll
            for (int hi = 0; hi < 2; hi++) {
                float vm = -1e30f;
                #pragma unroll
                for (int nt = 0; nt < 4; nt++)
                    vm = fmaxf(vm, fmaxf(s[mt][nt][2*hi], s[mt][nt][2*hi+1]));
                vm = fmaxf(vm, __shfl_xor_sync(0xffffffffu, vm, 1));
                vm = fmaxf(vm, __shfl_xor_sync(0xffffffffu, vm, 2));
                if (tig == 0) pmax[(wm*32 + mt*16 + g + 8*hi) * 2 + wn] = vm;
            }
        __syncthreads();

        float f[2][2];
        #pragma unroll
        for (int mt = 0; mt < 2; mt++)
            #pragma unroll
            for (int hi = 0; hi < 2; hi++) {
                const int R = wm*32 + mt*16 + g + 8*hi;
                float gm = fmaxf(pmax[R*2], pmax[R*2 + 1]);
                float mo = mst[mt][hi];
                float mn = fmaxf(mo, gm);
                float ff = __expf(mo - mn);
                f[mt][hi] = ff;
                float rs = 0.f;
                #pragma unroll
                for (int nt = 0; nt < 4; nt++) {
                    float p0 = __expf(s[mt][nt][2*hi]     - mn);
                    float p1 = __expf(s[mt][nt][2*hi + 1] - mn);
                    rs += p0 + p1;
                    unsigned hw, lw;
                    split_pack(p0, p1, hw, lw);
                    const int wi = R * 36 + wn*16 + nt*4 + tig;
                    Ph[wi] = hw;
                    Pl[wi] = lw;
                }
                rs += __shfl_xor_sync(0xffffffffu, rs, 1);
                rs += __shfl_xor_sync(0xffffffffu, rs, 2);
                if (tig == 0) psum[R*2 + wn] = rs;
                mst[mt][hi] = mn;
                #pragma unroll
                for (int nt = 0; nt < 4; nt++) {
                    o[mt][nt][2*hi]     *= ff;
                    o[mt][nt][2*hi + 1] *= ff;
                }
            }
        __syncthreads();
        #pragma unroll
        for (int mt = 0; mt < 2; mt++)
            #pragma unroll
            for (int hi = 0; hi < 2; hi++) {
                const int R = wm*32 + mt*16 + g + 8*hi;
                lst[mt][hi] = lst[mt][hi] * f[mt][hi] + psum[R*2] + psum[R*2 + 1];
            }

        // O += P @ V
        #pragma unroll
        for (int c2 = 0; c2 < 4; c2++) {
            const int base = c2 * 8;
            unsigned ah[2][4], al[2][4], bhf[4][2], blf[4][2];
            #pragma unroll
            for (int mt = 0; mt < 2; mt++) {
                const int rb = wm * 32 + mt * 16;
                ah[mt][0] = Ph[(rb + g    ) * 36 + base + tig    ];
                ah[mt][1] = Ph[(rb + g + 8) * 36 + base + tig    ];
                ah[mt][2] = Ph[(rb + g    ) * 36 + base + tig + 4];
                ah[mt][3] = Ph[(rb + g + 8) * 36 + base + tig + 4];
                al[mt][0] = Pl[(rb + g    ) * 36 + base + tig    ];
                al[mt][1] = Pl[(rb + g + 8) * 36 + base + tig    ];
                al[mt][2] = Pl[(rb + g    ) * 36 + base + tig + 4];
                al[mt][3] = Pl[(rb + g + 8) * 36 + base + tig + 4];
            }
            #pragma unroll
            for (int nt = 0; nt < 4; nt++) {
                const int n = wn * 32 + nt * 8 + g;
                bhf[nt][0] = Vh[n * 36 + base + tig    ];
                bhf[nt][1] = Vh[n * 36 + base + tig + 4];
                blf[nt][0] = Vl[n * 36 + base + tig    ];
                blf[nt][1] = Vl[n * 36 + base + tig + 4];
            }
            #pragma unroll
            for (int mt = 0; mt < 2; mt++)
                #pragma unroll
                for (int nt = 0; nt < 4; nt++) {
                    mma_bf16(o[mt][nt], ah[mt], bhf[nt]);
                    mma_bf16(o[mt][nt], al[mt], bhf[nt]);
                    mma_bf16(o[mt][nt], ah[mt], blf[nt]);
                }
        }
    }

    const int b = bh >> 4, h = bh & 15;
    #pragma unroll
    for (int mt = 0; mt < 2; mt++)
        #pragma unroll
        for (int hi = 0; hi < 2; hi++) {
            const int R = wm*32 + mt*16 + g + 8*hi;
            const float inv = 1.f / lst[mt][hi];
            const size_t grow = (size_t)(b * SEQ + qt * 128 + R);
            #pragma unroll
            for (int nt = 0; nt < 4; nt++) {
                const int cc = wn*32 + nt*8 + 2*tig;
                float2 v;
                v.x = o[mt][nt][2*hi]     * inv;
                v.y = o[mt][nt][2*hi + 1] * inv;
                *(float2*)&g_heads[grow * DIM + h * HDIM + cc] = v;
            }
        }
}

// ---------------------------------------------------------------------------
// SIMT attention fallback (round-1 proven) — runs only if mma oracle failed.
// ---------------------------------------------------------------------------
__global__ __launch_bounds__(256) void attn_fix()
{
    if (g_flags[0][0] != 0) return;   // mma works -> nothing to do

    extern __shared__ float sm[];
    float* Qs = sm;
    float* Ks = Qs + 64 * 68;
    float* Vs = Ks + 64 * 68;
    float* Ps = Vs + 64 * 68;

    const int qt = blockIdx.x;
    const int bh = blockIdx.y;
    const float* Q = g_q + (size_t)bh * SEQ * HDIM;
    const float* K = g_k + (size_t)bh * SEQ * HDIM;
    const float* V = g_v + (size_t)bh * SEQ * HDIM;

    const int t  = threadIdx.x;
    const int tx = t & 15;
    const int ty = t >> 4;

    #pragma unroll
    for (int it = 0; it < 4; it++) {
        int fid = t + it * 256;
        int qr  = fid >> 4;
        int h4  = (fid & 15) * 4;
        float4 a = *(const float4*)&Q[(qt * 64 + qr) * HDIM + h4];
        Qs[(h4 + 0) * 68 + qr] = a.x * 0.125f;
        Qs[(h4 + 1) * 68 + qr] = a.y * 0.125f;
        Qs[(h4 + 2) * 68 + qr] = a.z * 0.125f;
        Qs[(h4 + 3) * 68 + qr] = a.w * 0.125f;
    }

    float o[4][4];
    float m[4], l[4];
    #pragma unroll
    for (int i = 0; i < 4; i++) {
        m[i] = -1e30f; l[i] = 0.f;
        #pragma unroll
        for (int j = 0; j < 4; j++) o[i][j] = 0.f;
    }

    for (int kt = 0; kt < SEQ / 64; kt++) {
        __syncthreads();
        #pragma unroll
        for (int it = 0; it < 4; it++) {
            int fid = t + it * 256;
            int kr  = fid >> 4;
            int h4  = (fid & 15) * 4;
            float4 a = *(const float4*)&K[(kt * 64 + kr) * HDIM + h4];
            Ks[(h4 + 0) * 68 + kr] = a.x;
            Ks[(h4 + 1) * 68 + kr] = a.y;
            Ks[(h4 + 2) * 68 + kr] = a.z;
            Ks[(h4 + 3) * 68 + kr] = a.w;
            float4 vv = *(const float4*)&V[(kt * 64 + kr) * HDIM + h4];
            *(float4*)&Vs[kr * 68 + h4] = vv;
        }
        __syncthreads();

        float s[4][4];
        #pragma unroll
        for (int i = 0; i < 4; i++)
            #pragma unroll
            for (int j = 0; j < 4; j++) s[i][j] = 0.f;

        #pragma unroll 8
        for (int kk = 0; kk < 64; kk++) {
            float4 av  = *(float4*)&Qs[kk * 68 + 4 * ty];
            float4 bv4 = *(float4*)&Ks[kk * 68 + 4 * tx];
            float ar[4] = {av.x, av.y, av.z, av.w};
            float br[4] = {bv4.x, bv4.y, bv4.z, bv4.w};
            #pragma unroll
            for (int i = 0; i < 4; i++)
                #pragma unroll
                for (int j = 0; j < 4; j++)
                    s[i][j] = fmaf(ar[i], br[j], s[i][j]);
        }

        float p[4][4];
        #pragma unroll
        for (int i = 0; i < 4; i++) {
            float rm = fmaxf(fmaxf(s[i][0], s[i][1]), fmaxf(s[i][2], s[i][3]));
            #pragma unroll
            for (int off = 8; off >= 1; off >>= 1)
                rm = fmaxf(rm, __shfl_xor_sync(0xffffffffu, rm, off));
            float mn = fmaxf(m[i], rm);
            float f  = __expf(m[i] - mn);
            float rs = 0.f;
            #pragma unroll
            for (int j = 0; j < 4; j++) {
                p[i][j] = __expf(s[i][j] - mn);
                rs += p[i][j];
            }
            #pragma unroll
            for (int off = 8; off >= 1; off >>= 1)
                rs += __shfl_xor_sync(0xffffffffu, rs, off);
            l[i] = l[i] * f + rs;
            m[i] = mn;
            #pragma unroll
            for (int j = 0; j < 4; j++) o[i][j] *= f;
        }

        #pragma unroll
        for (int j = 0; j < 4; j++) {
            float4 col;
            col.x = p[0][j]; col.y = p[1][j]; col.z = p[2][j]; col.w = p[3][j];
            *(float4*)&Ps[(4 * tx + j) * 68 + 4 * ty] = col;
        }
        __syncthreads();

        #pragma unroll 8
        for (int kk = 0; kk < 64; kk++) {
            float4 av  = *(float4*)&Ps[kk * 68 + 4 * ty];
            float4 bv4 = *(float4*)&Vs[kk * 68 + 4 * tx];
            float ar[4] = {av.x, av.y, av.z, av.w};
            float br[4] = {bv4.x, bv4.y, bv4.z, bv4.w};
            #pragma unroll
            for (int i = 0; i < 4; i++)
                #pragma unroll
                for (int j = 0; j < 4; j++)
                    o[i][j] = fmaf(ar[i], br[j], o[i][j]);
        }
    }

    const int b = bh >> 4, h = bh & 15;
    #pragma unroll
    for (int i = 0; i < 4; i++) {
        float inv = 1.f / l[i];
        int srow = qt * 64 + 4 * ty + i;
        float4 v;
        v.x = o[i][0] * inv;
        v.y = o[i][1] * inv;
        v.z = o[i][2] * inv;
        v.w = o[i][3] * inv;
        *(float4*)&g_heads[((size_t)(b * SEQ + srow)) * DIM + h * HDIM + 4 * tx] = v;
    }
}

#define ATTN_SMEM ((36*(128+128+64+64+64+64+128+128) + 512) * (int)sizeof(unsigned))
#define ATTN_FIX_SMEM (4 * 64 * 68 * (int)sizeof(float))

extern "C" void kernel_launch(void* const* d_in, const int* in_sizes, int n_in,
                              void* d_out, int out_size)
{
    const float* x  = (const float*)d_in[0];
    const float* Wq = (const float*)d_in[1];
    const float* bq = (const float*)d_in[2];
    const float* Wk = (const float*)d_in[3];
    const float* bk = (const float*)d_in[4];
    const float* Wv = (const float*)d_in[5];
    const float* bv = (const float*)d_in[6];
    const float* Wo = (const float*)d_in[7];
    const float* bo = (const float*)d_in[8];
    float* out = (float*)d_out;

    cudaFuncSetAttribute(attn_mma,
                         cudaFuncAttributeMaxDynamicSharedMemorySize, ATTN_SMEM);
    cudaFuncSetAttribute(attn_fix,
                         cudaFuncAttributeMaxDynamicSharedMemorySize, ATTN_FIX_SMEM);

    const dim3 pgm(MROWS / 128, HEADS);   // mma grid (64,16)
    const dim3 pgf(MROWS / 64, HEADS);    // fix grid (128,16)

    proj_mma<true><<<pgm, 256>>>(x, Wq, bq, nullptr, 0, 0);
    proj_fix<true><<<pgf, 256>>>(x, Wq, bq, nullptr, 0, 0);
    proj_mma<true><<<pgm, 256>>>(x, Wk, bk, nullptr, 1, 1);
    proj_fix<true><<<pgf, 256>>>(x, Wk, bk, nullptr, 1, 1);
    proj_mma<true><<<pgm, 256>>>(x, Wv, bv, nullptr, 2, 2);
    proj_fix<true><<<pgf, 256>>>(x, Wv, bv, nullptr, 2, 2);

    attn_mma<<<dim3(SEQ / 128, BATCH * HEADS), 256, ATTN_SMEM>>>();
    attn_fix<<<dim3(SEQ / 64, BATCH * HEADS), 256, ATTN_FIX_SMEM>>>();

    proj_mma<false><<<pgm, 256>>>(nullptr, Wo, bo, out, 0, 3);
    proj_fix<false><<<pgf, 256>>>(nullptr, Wo, bo, out, 0, 3);
}

// round 10
// speedup vs baseline: 2.0304x; 1.2087x over previous
#include <cuda_runtime.h>
#include <cuda_bf16.h>
#include <cstdint>
#include <math.h>

#define BATCH 4
#define SEQ   2048
#define DIM   1024
#define HEADS 16
#define HDIM  64
#define MROWS (BATCH*SEQ)

// Scratch (no cudaMalloc). Referenced ONLY inside device code.
// All intermediates live as split bf16 hi/lo planes.
__device__ unsigned short g_xh[MROWS*DIM], g_xl[MROWS*DIM];      // x split
__device__ unsigned short g_wth[4*DIM*DIM], g_wtl[4*DIM*DIM];    // W^T split [n][k]
__device__ unsigned short g_qh[MROWS*DIM], g_ql[MROWS*DIM];      // [bh][s][hd]
__device__ unsigned short g_kh[MROWS*DIM], g_kl[MROWS*DIM];      // [bh][s][hd]
__device__ unsigned short g_vh[MROWS*DIM], g_vl[MROWS*DIM];      // [bh][hd][s]
__device__ unsigned short g_hh[MROWS*DIM], g_hl[MROWS*DIM];      // heads [r][D]

// ---------------------------------------------------------------------------
__device__ __forceinline__ void mma_bf16(float c[4], const unsigned a[4], const unsigned b[2]) {
    asm volatile(
        "mma.sync.aligned.m16n8k16.row.col.f32.bf16.bf16.f32 "
        "{%0,%1,%2,%3},{%4,%5,%6,%7},{%8,%9},{%0,%1,%2,%3};"
        : "+f"(c[0]), "+f"(c[1]), "+f"(c[2]), "+f"(c[3])
        : "r"(a[0]), "r"(a[1]), "r"(a[2]), "r"(a[3]), "r"(b[0]), "r"(b[1]));
}

__device__ __forceinline__ void split1(float x, unsigned short &h, unsigned short &l) {
    __nv_bfloat16 hb = __float2bfloat16(x);
    __nv_bfloat16 lb = __float2bfloat16(x - __bfloat162float(hb));
    h = *(const unsigned short*)&hb;
    l = *(const unsigned short*)&lb;
}

__device__ __forceinline__ void split_pack(float x0, float x1, unsigned &hw, unsigned &lw) {
    unsigned short h0, l0, h1, l1;
    split1(x0, h0, l0);
    split1(x1, h1, l1);
    hw = (unsigned)h0 | ((unsigned)h1 << 16);
    lw = (unsigned)l0 | ((unsigned)l1 << 16);
}

// ---------------------------------------------------------------------------
// prep_x: split x into bf16 hi/lo planes. One float4 per thread.
// ---------------------------------------------------------------------------
__global__ __launch_bounds__(256) void prep_x(const float* __restrict__ x)
{
    const size_t i = (size_t)blockIdx.x * 256 + threadIdx.x;   // float4 id
    float4 v = *(const float4*)&x[i * 4];
    unsigned h0, l0, h1, l1;
    split_pack(v.x, v.y, h0, l0);
    split_pack(v.z, v.w, h1, l1);
    ((uint2*)g_xh)[i] = make_uint2(h0, h1);
    ((uint2*)g_xl)[i] = make_uint2(l0, l1);
}

// ---------------------------------------------------------------------------
// prep_w: split + transpose weights -> g_wt[widx][n][k] bf16 planes.
// grid (16,16,4): 64x64 tile per block; z selects the matrix.
// ---------------------------------------------------------------------------
__global__ __launch_bounds__(256) void prep_w(
    const float* __restrict__ Wq, const float* __restrict__ Wk,
    const float* __restrict__ Wv, const float* __restrict__ Wo)
{
    __shared__ unsigned short Th[64][65], Tl[64][65];
    const int widx = blockIdx.z;
    const float* W = (widx == 0) ? Wq : (widx == 1) ? Wk : (widx == 2) ? Wv : Wo;

    const int t  = threadIdx.x;
    const int k0 = blockIdx.x * 64;
    const int n0 = blockIdx.y * 64;

    const int r0 = t >> 4;           // 0..15
    const int c4 = (t & 15) * 4;     // 0..60
    #pragma unroll
    for (int rr = 0; rr < 4; rr++) {
        const int r = r0 + rr * 16;
        float4 v = *(const float4*)&W[(size_t)(k0 + r) * DIM + n0 + c4];
        float vv[4] = {v.x, v.y, v.z, v.w};
        #pragma unroll
        for (int j = 0; j < 4; j++) {
            unsigned short h, l;
            split1(vv[j], h, l);
            Th[c4 + j][r] = h;
            Tl[c4 + j][r] = l;
        }
    }
    __syncthreads();

    unsigned* dh = (unsigned*)g_wth + (size_t)widx * (DIM * DIM / 2);
    unsigned* dl = (unsigned*)g_wtl + (size_t)widx * (DIM * DIM / 2);
    const int n    = t >> 2;         // 0..63
    const int part = (t & 3) * 8;    // word part
    #pragma unroll
    for (int j = 0; j < 8; j++) {
        const int w = part + j;
        unsigned hw = (unsigned)Th[n][2*w] | ((unsigned)Th[n][2*w + 1] << 16);
        unsigned lw = (unsigned)Tl[n][2*w] | ((unsigned)Tl[n][2*w + 1] << 16);
        const size_t di = (size_t)(n0 + n) * (DIM / 2) + (k0 >> 1) + w;
        dh[di] = hw;
        dl[di] = lw;
    }
}

// ---------------------------------------------------------------------------
// Projection GEMM: C = A @ W + bias. Block 128x64, Ktile=32 (16 words).
// 8 warps: 4 along M, 2 along N. MODE: 0=Q (scaled), 1=K, 2=V (transposed
// split out), 3=O (float out, A = heads planes). Weight index == MODE.
// ---------------------------------------------------------------------------
template<int MODE>
__global__ __launch_bounds__(256) void proj(
    const float* __restrict__ bias, float* __restrict__ outp)
{
    const unsigned* Ah = (const unsigned*)((MODE == 3) ? g_hh : g_xh);
    const unsigned* Al = (const unsigned*)((MODE == 3) ? g_hl : g_xl);
    const unsigned* Wh = (const unsigned*)g_wth + (size_t)MODE * (DIM * DIM / 2);
    const unsigned* Wl = (const unsigned*)g_wtl + (size_t)MODE * (DIM * DIM / 2);

    __shared__ __align__(16) unsigned Ahw[128*20], Alw[128*20];
    __shared__ __align__(16) unsigned Bhw[64*20],  Blw[64*20];

    const int t    = threadIdx.x;
    const int lane = t & 31;
    const int w    = t >> 5;
    const int g    = lane >> 2;
    const int tig  = lane & 3;
    const int wm   = w & 3;
    const int wn   = w >> 2;
    const int row0 = blockIdx.x * 128;
    const int col0 = blockIdx.y * 64;

    // staging maps
    const int ar = t >> 1;           // A row 0..127
    const int ap = (t & 1) * 8;      // A word part
    const int br = t & 63;           // B row (n) 0..63
    const int bp = (t >> 6) * 4;     // B word part

    const size_t abase = (size_t)(row0 + ar) * (DIM / 2) + ap;
    const size_t bbase = (size_t)(col0 + br) * (DIM / 2) + bp;

    float c[2][4][4];
    #pragma unroll
    for (int mt = 0; mt < 2; mt++)
        #pragma unroll
        for (int nt = 0; nt < 4; nt++)
            #pragma unroll
            for (int i = 0; i < 4; i++) c[mt][nt][i] = 0.f;

    uint4 pah0, pah1, pal0, pal1, pbh, pbl;
    pah0 = *(const uint4*)&Ah[abase];
    pah1 = *(const uint4*)&Ah[abase + 4];
    pal0 = *(const uint4*)&Al[abase];
    pal1 = *(const uint4*)&Al[abase + 4];
    pbh  = *(const uint4*)&Wh[bbase];
    pbl  = *(const uint4*)&Wl[bbase];

    for (int k0 = 0; k0 < DIM; k0 += 32) {
        *(uint4*)&Ahw[ar * 20 + ap]     = pah0;
        *(uint4*)&Ahw[ar * 20 + ap + 4] = pah1;
        *(uint4*)&Alw[ar * 20 + ap]     = pal0;
        *(uint4*)&Alw[ar * 20 + ap + 4] = pal1;
        *(uint4*)&Bhw[br * 20 + bp]     = pbh;
        *(uint4*)&Blw[br * 20 + bp]     = pbl;
        __syncthreads();

        if (k0 + 32 < DIM) {
            const size_t ai = abase + ((k0 + 32) >> 1);
            const size_t bi = bbase + ((k0 + 32) >> 1);
            pah0 = *(const uint4*)&Ah[ai];
            pah1 = *(const uint4*)&Ah[ai + 4];
            pal0 = *(const uint4*)&Al[ai];
            pal1 = *(const uint4*)&Al[ai + 4];
            pbh  = *(const uint4*)&Wh[bi];
            pbl  = *(const uint4*)&Wl[bi];
        }

        #pragma unroll
        for (int c2 = 0; c2 < 2; c2++) {
            const int base = c2 * 8;
            unsigned ah[2][4], al[2][4], bh[4][2], bl[4][2];
            #pragma unroll
            for (int mt = 0; mt < 2; mt++) {
                const int rb = wm * 32 + mt * 16;
                ah[mt][0] = Ahw[(rb + g    ) * 20 + base + tig    ];
                ah[mt][1] = Ahw[(rb + g + 8) * 20 + base + tig    ];
                ah[mt][2] = Ahw[(rb + g    ) * 20 + base + tig + 4];
                ah[mt][3] = Ahw[(rb + g + 8) * 20 + base + tig + 4];
                al[mt][0] = Alw[(rb + g    ) * 20 + base + tig    ];
                al[mt][1] = Alw[(rb + g + 8) * 20 + base + tig    ];
                al[mt][2] = Alw[(rb + g    ) * 20 + base + tig + 4];
                al[mt][3] = Alw[(rb + g + 8) * 20 + base + tig + 4];
            }
            #pragma unroll
            for (int nt = 0; nt < 4; nt++) {
                const int n = wn * 32 + nt * 8 + g;
                bh[nt][0] = Bhw[n * 20 + base + tig    ];
                bh[nt][1] = Bhw[n * 20 + base + tig + 4];
                bl[nt][0] = Blw[n * 20 + base + tig    ];
                bl[nt][1] = Blw[n * 20 + base + tig + 4];
            }
            #pragma unroll
            for (int mt = 0; mt < 2; mt++)
                #pragma unroll
                for (int nt = 0; nt < 4; nt++) {
                    mma_bf16(c[mt][nt], ah[mt], bh[nt]);
                    mma_bf16(c[mt][nt], al[mt], bh[nt]);
                    mma_bf16(c[mt][nt], ah[mt], bl[nt]);
                }
        }
        __syncthreads();
    }

    // epilogue
    #pragma unroll
    for (int nt = 0; nt < 4; nt++) {
        const int cloc = wn * 32 + nt * 8 + 2 * tig;
        const int cc   = col0 + cloc;
        float2 bb = *(const float2*)&bias[cc];
        #pragma unroll
        for (int mt = 0; mt < 2; mt++) {
            #pragma unroll
            for (int hi = 0; hi < 2; hi++) {
                const int r = row0 + wm * 32 + mt * 16 + g + 8 * hi;
                float vx = c[mt][nt][2*hi]     + bb.x;
                float vy = c[mt][nt][2*hi + 1] + bb.y;
                if (MODE == 0) { vx *= 0.125f; vy *= 0.125f; }   // fold 1/sqrt(64)
                if (MODE == 0 || MODE == 1) {
                    const int b = r >> 11;
                    const int s = r & 2047;
                    const size_t wi = ((size_t)(b * HEADS + blockIdx.y) * SEQ + s) * 32
                                      + (cloc >> 1);
                    unsigned hw, lw;
                    split_pack(vx, vy, hw, lw);
                    if (MODE == 0) { ((unsigned*)g_qh)[wi] = hw; ((unsigned*)g_ql)[wi] = lw; }
                    else           { ((unsigned*)g_kh)[wi] = hw; ((unsigned*)g_kl)[wi] = lw; }
                } else if (MODE == 2) {
                    const int b = r >> 11;
                    const int s = r & 2047;
                    const size_t bhh = (size_t)(b * HEADS + blockIdx.y) * HDIM;
                    unsigned short h0, l0, h1, l1;
                    split1(vx, h0, l0);
                    split1(vy, h1, l1);
                    g_vh[(bhh + cloc)     * SEQ + s] = h0;
                    g_vl[(bhh + cloc)     * SEQ + s] = l0;
                    g_vh[(bhh + cloc + 1) * SEQ + s] = h1;
                    g_vl[(bhh + cloc + 1) * SEQ + s] = l1;
                } else {
                    *(float2*)&outp[(size_t)r * DIM + cc] = make_float2(vx, vy);
                }
            }
        }
    }
}

// ---------------------------------------------------------------------------
// Flash attention, split-bf16 mma on pre-split planes. Block: 128 q x (b,h).
// 8 warps (4M x 2N), 32 key-tiles of 64.
// ---------------------------------------------------------------------------
__global__ __launch_bounds__(256) void attn_mma()
{
    extern __shared__ __align__(16) unsigned smw[];
    unsigned* Qh = smw;
    unsigned* Ql = Qh + 128*36;
    unsigned* Kh = Ql + 128*36;
    unsigned* Kl = Kh + 64*36;
    unsigned* Vh = Kl + 64*36;       // [hd][key words]
    unsigned* Vl = Vh + 64*36;
    unsigned* Ph = Vl + 64*36;
    unsigned* Pl = Ph + 128*36;
    float* pmax = (float*)(Pl + 128*36);
    float* psum = pmax + 256;

    const int t    = threadIdx.x;
    const int lane = t & 31;
    const int w    = t >> 5;
    const int g    = lane >> 2;
    const int tig  = lane & 3;
    const int wm   = w & 3;
    const int wn   = w >> 2;
    const int qt   = blockIdx.x;
    const int bh   = blockIdx.y;

    const unsigned* Qgh = (const unsigned*)g_qh + (size_t)bh * SEQ * 32;
    const unsigned* Qgl = (const unsigned*)g_ql + (size_t)bh * SEQ * 32;
    const unsigned* Kgh = (const unsigned*)g_kh + (size_t)bh * SEQ * 32;
    const unsigned* Kgl = (const unsigned*)g_kl + (size_t)bh * SEQ * 32;
    const unsigned* Vgh = (const unsigned*)g_vh + (size_t)bh * HDIM * (SEQ / 2);
    const unsigned* Vgl = (const unsigned*)g_vl + (size_t)bh * HDIM * (SEQ / 2);

    // stage Q (pre-scaled in proj<0>)
    {
        const int r    = t >> 1;
        const int half = (t & 1) * 16;
        const size_t gi = (size_t)(qt * 128 + r) * 32 + half;
        #pragma unroll
        for (int j = 0; j < 4; j++) {
            *(uint4*)&Qh[r * 36 + half + j * 4] = *(const uint4*)&Qgh[gi + j * 4];
            *(uint4*)&Ql[r * 36 + half + j * 4] = *(const uint4*)&Qgl[gi + j * 4];
        }
    }

    float mst[2][2], lst[2][2], o[2][4][4];
    #pragma unroll
    for (int mt = 0; mt < 2; mt++)
        #pragma unroll
        for (int hi = 0; hi < 2; hi++) { mst[mt][hi] = -1e30f; lst[mt][hi] = 0.f; }
    #pragma unroll
    for (int mt = 0; mt < 2; mt++)
        #pragma unroll
        for (int nt = 0; nt < 4; nt++)
            #pragma unroll
            for (int i = 0; i < 4; i++) o[mt][nt][i] = 0.f;

    const int sr = t >> 2;           // staging row 0..63
    const int sp = (t & 3) * 8;      // word part

    for (int kt = 0; kt < SEQ / 64; kt++) {
        __syncthreads();
        {
            const size_t ki = (size_t)(kt * 64 + sr) * 32 + sp;
            *(uint4*)&Kh[sr * 36 + sp]     = *(const uint4*)&Kgh[ki];
            *(uint4*)&Kh[sr * 36 + sp + 4] = *(const uint4*)&Kgh[ki + 4];
            *(uint4*)&Kl[sr * 36 + sp]     = *(const uint4*)&Kgl[ki];
            *(uint4*)&Kl[sr * 36 + sp + 4] = *(const uint4*)&Kgl[ki + 4];
            const size_t vi = (size_t)sr * (SEQ / 2) + kt * 32 + sp;
            *(uint4*)&Vh[sr * 36 + sp]     = *(const uint4*)&Vgh[vi];
            *(uint4*)&Vh[sr * 36 + sp + 4] = *(const uint4*)&Vgh[vi + 4];
            *(uint4*)&Vl[sr * 36 + sp]     = *(const uint4*)&Vgl[vi];
            *(uint4*)&Vl[sr * 36 + sp + 4] = *(const uint4*)&Vgl[vi + 4];
        }
        __syncthreads();

        // S = Q @ K^T
        float s[2][4][4];
        #pragma unroll
        for (int mt = 0; mt < 2; mt++)
            #pragma unroll
            for (int nt = 0; nt < 4; nt++)
                #pragma unroll
                for (int i = 0; i < 4; i++) s[mt][nt][i] = 0.f;

        #pragma unroll
        for (int c2 = 0; c2 < 4; c2++) {
            const int base = c2 * 8;
            unsigned ah[2][4], al[2][4], bhf[4][2], blf[4][2];
            #pragma unroll
            for (int mt = 0; mt < 2; mt++) {
                const int rb = wm * 32 + mt * 16;
                ah[mt][0] = Qh[(rb + g    ) * 36 + base + tig    ];
                ah[mt][1] = Qh[(rb + g + 8) * 36 + base + tig    ];
                ah[mt][2] = Qh[(rb + g    ) * 36 + base + tig + 4];
                ah[mt][3] = Qh[(rb + g + 8) * 36 + base + tig + 4];
                al[mt][0] = Ql[(rb + g    ) * 36 + base + tig    ];
                al[mt][1] = Ql[(rb + g + 8) * 36 + base + tig    ];
                al[mt][2] = Ql[(rb + g    ) * 36 + base + tig + 4];
                al[mt][3] = Ql[(rb + g + 8) * 36 + base + tig + 4];
            }
            #pragma unroll
            for (int nt = 0; nt < 4; nt++) {
                const int n = wn * 32 + nt * 8 + g;
                bhf[nt][0] = Kh[n * 36 + base + tig    ];
                bhf[nt][1] = Kh[n * 36 + base + tig + 4];
                blf[nt][0] = Kl[n * 36 + base + tig    ];
                blf[nt][1] = Kl[n * 36 + base + tig + 4];
            }
            #pragma unroll
            for (int mt = 0; mt < 2; mt++)
                #pragma unroll
                for (int nt = 0; nt < 4; nt++) {
                    mma_bf16(s[mt][nt], ah[mt], bhf[nt]);
                    mma_bf16(s[mt][nt], al[mt], bhf[nt]);
                    mma_bf16(s[mt][nt], ah[mt], blf[nt]);
                }
        }

        // online softmax
        #pragma unroll
        for (int mt = 0; mt < 2; mt++)
            #pragma unroll
            for (int hi = 0; hi < 2; hi++) {
                float vm = -1e30f;
                #pragma unroll
                for (int nt = 0; nt < 4; nt++)
                    vm = fmaxf(vm, fmaxf(s[mt][nt][2*hi], s[mt][nt][2*hi+1]));
                vm = fmaxf(vm, __shfl_xor_sync(0xffffffffu, vm, 1));
                vm = fmaxf(vm, __shfl_xor_sync(0xffffffffu, vm, 2));
                if (tig == 0) pmax[(wm*32 + mt*16 + g + 8*hi) * 2 + wn] = vm;
            }
        __syncthreads();

        float f[2][2];
        #pragma unroll
        for (int mt = 0; mt < 2; mt++)
            #pragma unroll
            for (int hi = 0; hi < 2; hi++) {
                const int R = wm*32 + mt*16 + g + 8*hi;
                float gm = fmaxf(pmax[R*2], pmax[R*2 + 1]);
                float mo = mst[mt][hi];
                float mn = fmaxf(mo, gm);
                float ff = __expf(mo - mn);
                f[mt][hi] = ff;
                float rs = 0.f;
                #pragma unroll
                for (int nt = 0; nt < 4; nt++) {
                    float p0 = __expf(s[mt][nt][2*hi]     - mn);
                    float p1 = __expf(s[mt][nt][2*hi + 1] - mn);
                    rs += p0 + p1;
                    unsigned hw, lw;
                    split_pack(p0, p1, hw, lw);
                    const int wi = R * 36 + wn*16 + nt*4 + tig;
                    Ph[wi] = hw;
                    Pl[wi] = lw;
                }
                rs += __shfl_xor_sync(0xffffffffu, rs, 1);
                rs += __shfl_xor_sync(0xffffffffu, rs, 2);
                if (tig == 0) psum[R*2 + wn] = rs;
                mst[mt][hi] = mn;
                #pragma unroll
                for (int nt = 0; nt < 4; nt++) {
                    o[mt][nt][2*hi]     *= ff;
                    o[mt][nt][2*hi + 1] *= ff;
                }
            }
        __syncthreads();
        #pragma unroll
        for (int mt = 0; mt < 2; mt++)
            #pragma unroll
            for (int hi = 0; hi < 2; hi++) {
                const int R = wm*32 + mt*16 + g + 8*hi;
                lst[mt][hi] = lst[mt][hi] * f[mt][hi] + psum[R*2] + psum[R*2 + 1];
            }

        // O += P @ V
        #pragma unroll
        for (int c2 = 0; c2 < 4; c2++) {
            const int base = c2 * 8;
            unsigned ah[2][4], al[2][4], bhf[4][2], blf[4][2];
            #pragma unroll
            for (int mt = 0; mt < 2; mt++) {
                const int rb = wm * 32 + mt * 16;
                ah[mt][0] = Ph[(rb + g    ) * 36 + base + tig    ];
                ah[mt][1] = Ph[(rb + g + 8) * 36 + base + tig    ];
                ah[mt][2] = Ph[(rb + g    ) * 36 + base + tig + 4];
                ah[mt][3] = Ph[(rb + g + 8) * 36 + base + tig + 4];
                al[mt][0] = Pl[(rb + g    ) * 36 + base + tig    ];
                al[mt][1] = Pl[(rb + g + 8) * 36 + base + tig    ];
                al[mt][2] = Pl[(rb + g    ) * 36 + base + tig + 4];
                al[mt][3] = Pl[(rb + g + 8) * 36 + base + tig + 4];
            }
            #pragma unroll
            for (int nt = 0; nt < 4; nt++) {
                const int n = wn * 32 + nt * 8 + g;
                bhf[nt][0] = Vh[n * 36 + base + tig    ];
                bhf[nt][1] = Vh[n * 36 + base + tig + 4];
                blf[nt][0] = Vl[n * 36 + base + tig    ];
                blf[nt][1] = Vl[n * 36 + base + tig + 4];
            }
            #pragma unroll
            for (int mt = 0; mt < 2; mt++)
                #pragma unroll
                for (int nt = 0; nt < 4; nt++) {
                    mma_bf16(o[mt][nt], ah[mt], bhf[nt]);
                    mma_bf16(o[mt][nt], al[mt], bhf[nt]);
                    mma_bf16(o[mt][nt], ah[mt], blf[nt]);
                }
        }
    }

    // finalize -> split heads planes
    const int b = bh >> 4, h = bh & 15;
    #pragma unroll
    for (int mt = 0; mt < 2; mt++)
        #pragma unroll
        for (int hi = 0; hi < 2; hi++) {
            const int R = wm*32 + mt*16 + g + 8*hi;
            const float inv = 1.f / lst[mt][hi];
            const size_t grow = (size_t)(b * SEQ + qt * 128 + R);
            #pragma unroll
            for (int nt = 0; nt < 4; nt++) {
                const int cc = wn*32 + nt*8 + 2*tig;
                float vx = o[mt][nt][2*hi]     * inv;
                float vy = o[mt][nt][2*hi + 1] * inv;
                unsigned hw, lw;
                split_pack(vx, vy, hw, lw);
                const size_t wi = grow * (DIM / 2) + ((h * HDIM + cc) >> 1);
                ((unsigned*)g_hh)[wi] = hw;
                ((unsigned*)g_hl)[wi] = lw;
            }
        }
}

#define ATTN_SMEM ((36*(128+128+64+64+64+64+128+128) + 512) * (int)sizeof(unsigned))

extern "C" void kernel_launch(void* const* d_in, const int* in_sizes, int n_in,
                              void* d_out, int out_size)
{
    const float* x  = (const float*)d_in[0];
    const float* Wq = (const float*)d_in[1];
    const float* bq = (const float*)d_in[2];
    const float* Wk = (const float*)d_in[3];
    const float* bk = (const float*)d_in[4];
    const float* Wv = (const float*)d_in[5];
    const float* bv = (const float*)d_in[6];
    const float* Wo = (const float*)d_in[7];
    const float* bo = (const float*)d_in[8];
    float* out = (float*)d_out;

    cudaFuncSetAttribute(attn_mma,
                         cudaFuncAttributeMaxDynamicSharedMemorySize, ATTN_SMEM);

    prep_x<<<(MROWS * DIM / 4) / 256, 256>>>(x);
    prep_w<<<dim3(DIM / 64, DIM / 64, 4), 256>>>(Wq, Wk, Wv, Wo);

    const dim3 pg(MROWS / 128, HEADS);
    proj<0><<<pg, 256>>>(bq, nullptr);
    proj<1><<<pg, 256>>>(bk, nullptr);
    proj<2><<<pg, 256>>>(bv, nullptr);

    attn_mma<<<dim3(SEQ / 128, BATCH * HEADS), 256, ATTN_SMEM>>>();

    proj<3><<<pg, 256>>>(bo, out);
}

// round 12
// speedup vs baseline: 2.3255x; 1.1453x over previous
#include <cuda_runtime.h>
#include <cuda_bf16.h>
#include <cstdint>
#include <math.h>

#define BATCH 4
#define SEQ   2048
#define DIM   1024
#define HEADS 16
#define HDIM  64
#define MROWS (BATCH*SEQ)

// Scratch (no cudaMalloc). Referenced ONLY inside device code.
__device__ unsigned short g_xh[MROWS*DIM], g_xl[MROWS*DIM];      // x split
__device__ unsigned short g_wth[4*DIM*DIM], g_wtl[4*DIM*DIM];    // W^T split [n][k]
__device__ unsigned short g_qh[MROWS*DIM], g_ql[MROWS*DIM];      // [bh][s][hd]
__device__ unsigned short g_kh[MROWS*DIM], g_kl[MROWS*DIM];      // [bh][s][hd]
__device__ unsigned short g_vh[MROWS*DIM], g_vl[MROWS*DIM];      // [bh][hd][s]
__device__ unsigned short g_hh[MROWS*DIM], g_hl[MROWS*DIM];      // heads [r][D]

// ---------------------------------------------------------------------------
__device__ __forceinline__ void mma_bf16(float c[4], const unsigned a[4], const unsigned b[2]) {
    asm volatile(
        "mma.sync.aligned.m16n8k16.row.col.f32.bf16.bf16.f32 "
        "{%0,%1,%2,%3},{%4,%5,%6,%7},{%8,%9},{%0,%1,%2,%3};"
        : "+f"(c[0]), "+f"(c[1]), "+f"(c[2]), "+f"(c[3])
        : "r"(a[0]), "r"(a[1]), "r"(a[2]), "r"(a[3]), "r"(b[0]), "r"(b[1]));
}

__device__ __forceinline__ void ldsm_x4(unsigned r[4], uint32_t saddr) {
    asm volatile("ldmatrix.sync.aligned.m8n8.x4.shared.b16 {%0,%1,%2,%3}, [%4];"
        : "=r"(r[0]), "=r"(r[1]), "=r"(r[2]), "=r"(r[3]) : "r"(saddr));
}

__device__ __forceinline__ void split1(float x, unsigned short &h, unsigned short &l) {
    __nv_bfloat16 hb = __float2bfloat16(x);
    __nv_bfloat16 lb = __float2bfloat16(x - __bfloat162float(hb));
    h = *(const unsigned short*)&hb;
    l = *(const unsigned short*)&lb;
}

__device__ __forceinline__ void split_pack(float x0, float x1, unsigned &hw, unsigned &lw) {
    unsigned short h0, l0, h1, l1;
    split1(x0, h0, l0);
    split1(x1, h1, l1);
    hw = (unsigned)h0 | ((unsigned)h1 << 16);
    lw = (unsigned)l0 | ((unsigned)l1 << 16);
}

// ---------------------------------------------------------------------------
__global__ __launch_bounds__(256) void prep_x(const float* __restrict__ x)
{
    const size_t i = (size_t)blockIdx.x * 256 + threadIdx.x;
    float4 v = *(const float4*)&x[i * 4];
    unsigned h0, l0, h1, l1;
    split_pack(v.x, v.y, h0, l0);
    split_pack(v.z, v.w, h1, l1);
    ((uint2*)g_xh)[i] = make_uint2(h0, h1);
    ((uint2*)g_xl)[i] = make_uint2(l0, l1);
}

__global__ __launch_bounds__(256) void prep_w(
    const float* __restrict__ Wq, const float* __restrict__ Wk,
    const float* __restrict__ Wv, const float* __restrict__ Wo)
{
    __shared__ unsigned short Th[64][65], Tl[64][65];
    const int widx = blockIdx.z;
    const float* W = (widx == 0) ? Wq : (widx == 1) ? Wk : (widx == 2) ? Wv : Wo;

    const int t  = threadIdx.x;
    const int k0 = blockIdx.x * 64;
    const int n0 = blockIdx.y * 64;

    const int r0 = t >> 4;
    const int c4 = (t & 15) * 4;
    #pragma unroll
    for (int rr = 0; rr < 4; rr++) {
        const int r = r0 + rr * 16;
        float4 v = *(const float4*)&W[(size_t)(k0 + r) * DIM + n0 + c4];
        float vv[4] = {v.x, v.y, v.z, v.w};
        #pragma unroll
        for (int j = 0; j < 4; j++) {
            unsigned short h, l;
            split1(vv[j], h, l);
            Th[c4 + j][r] = h;
            Tl[c4 + j][r] = l;
        }
    }
    __syncthreads();

    unsigned* dh = (unsigned*)g_wth + (size_t)widx * (DIM * DIM / 2);
    unsigned* dl = (unsigned*)g_wtl + (size_t)widx * (DIM * DIM / 2);
    const int n    = t >> 2;
    const int part = (t & 3) * 8;
    #pragma unroll
    for (int j = 0; j < 8; j++) {
        const int w = part + j;
        unsigned hw = (unsigned)Th[n][2*w] | ((unsigned)Th[n][2*w + 1] << 16);
        unsigned lw = (unsigned)Tl[n][2*w] | ((unsigned)Tl[n][2*w + 1] << 16);
        const size_t di = (size_t)(n0 + n) * (DIM / 2) + (k0 >> 1) + w;
        dh[di] = hw;
        dl[di] = lw;
    }
}

// ---------------------------------------------------------------------------
// Projection GEMM: C = A @ W + bias. Block 128x64, Ktile=32 (16 words).
// Fragments via ldmatrix.x4. MODE: 0=Q(scaled) 1=K 2=V(transposed) 3=O(float).
// ---------------------------------------------------------------------------
template<int MODE>
__global__ __launch_bounds__(256) void proj(
    const float* __restrict__ bias, float* __restrict__ outp)
{
    const unsigned* Ah = (const unsigned*)((MODE == 3) ? g_hh : g_xh);
    const unsigned* Al = (const unsigned*)((MODE == 3) ? g_hl : g_xl);
    const unsigned* Wh = (const unsigned*)g_wth + (size_t)MODE * (DIM * DIM / 2);
    const unsigned* Wl = (const unsigned*)g_wtl + (size_t)MODE * (DIM * DIM / 2);

    __shared__ __align__(16) unsigned Ahw[128*20], Alw[128*20];
    __shared__ __align__(16) unsigned Bhw[64*20],  Blw[64*20];

    const int t    = threadIdx.x;
    const int lane = t & 31;
    const int w    = t >> 5;
    const int g    = lane >> 2;
    const int tig  = lane & 3;
    const int wm   = w & 3;
    const int wn   = w >> 2;
    const int row0 = blockIdx.x * 128;
    const int col0 = blockIdx.y * 64;

    // ldmatrix per-lane row/word bases
    const int lj = lane >> 3, lr = lane & 7;
    const int afr = wm * 32 + (lj & 1) * 8 + lr;   // + mt*16
    const int afw = (lj >> 1) * 4;
    const int bfn = wn * 32 + (lj >> 1) * 8 + lr;  // + pair*16
    const int bfw = (lj & 1) * 4;

    const uint32_t AhB = (uint32_t)__cvta_generic_to_shared(Ahw);
    const uint32_t AlB = (uint32_t)__cvta_generic_to_shared(Alw);
    const uint32_t BhB = (uint32_t)__cvta_generic_to_shared(Bhw);
    const uint32_t BlB = (uint32_t)__cvta_generic_to_shared(Blw);

    // staging maps
    const int ar = t >> 1;
    const int ap = (t & 1) * 8;
    const int br = t & 63;
    const int bp = (t >> 6) * 4;

    const size_t abase = (size_t)(row0 + ar) * (DIM / 2) + ap;
    const size_t bbase = (size_t)(col0 + br) * (DIM / 2) + bp;

    float c[2][4][4];
    #pragma unroll
    for (int mt = 0; mt < 2; mt++)
        #pragma unroll
        for (int nt = 0; nt < 4; nt++)
            #pragma unroll
            for (int i = 0; i < 4; i++) c[mt][nt][i] = 0.f;

    uint4 pah0, pah1, pal0, pal1, pbh, pbl;
    pah0 = *(const uint4*)&Ah[abase];
    pah1 = *(const uint4*)&Ah[abase + 4];
    pal0 = *(const uint4*)&Al[abase];
    pal1 = *(const uint4*)&Al[abase + 4];
    pbh  = *(const uint4*)&Wh[bbase];
    pbl  = *(const uint4*)&Wl[bbase];

    for (int k0 = 0; k0 < DIM; k0 += 32) {
        *(uint4*)&Ahw[ar * 20 + ap]     = pah0;
        *(uint4*)&Ahw[ar * 20 + ap + 4] = pah1;
        *(uint4*)&Alw[ar * 20 + ap]     = pal0;
        *(uint4*)&Alw[ar * 20 + ap + 4] = pal1;
        *(uint4*)&Bhw[br * 20 + bp]     = pbh;
        *(uint4*)&Blw[br * 20 + bp]     = pbl;
        __syncthreads();

        if (k0 + 32 < DIM) {
            const size_t ai = abase + ((k0 + 32) >> 1);
            const size_t bi = bbase + ((k0 + 32) >> 1);
            pah0 = *(const uint4*)&Ah[ai];
            pah1 = *(const uint4*)&Ah[ai + 4];
            pal0 = *(const uint4*)&Al[ai];
            pal1 = *(const uint4*)&Al[ai + 4];
            pbh  = *(const uint4*)&Wh[bi];
            pbl  = *(const uint4*)&Wl[bi];
        }

        #pragma unroll
        for (int c2 = 0; c2 < 2; c2++) {
            const int base = c2 * 8;
            unsigned ah[2][4], al[2][4], bh[4][2], bl[4][2];
            #pragma unroll
            for (int mt = 0; mt < 2; mt++) {
                const uint32_t off = ((afr + mt * 16) * 20 + base + afw) * 4;
                ldsm_x4(ah[mt], AhB + off);
                ldsm_x4(al[mt], AlB + off);
            }
            #pragma unroll
            for (int pr = 0; pr < 2; pr++) {
                const uint32_t off = ((bfn + pr * 16) * 20 + base + bfw) * 4;
                unsigned rh[4], rl[4];
                ldsm_x4(rh, BhB + off);
                ldsm_x4(rl, BlB + off);
                bh[pr*2][0] = rh[0]; bh[pr*2][1] = rh[1];
                bh[pr*2+1][0] = rh[2]; bh[pr*2+1][1] = rh[3];
                bl[pr*2][0] = rl[0]; bl[pr*2][1] = rl[1];
                bl[pr*2+1][0] = rl[2]; bl[pr*2+1][1] = rl[3];
            }
            #pragma unroll
            for (int mt = 0; mt < 2; mt++)
                #pragma unroll
                for (int nt = 0; nt < 4; nt++) {
                    mma_bf16(c[mt][nt], ah[mt], bh[nt]);
                    mma_bf16(c[mt][nt], al[mt], bh[nt]);
                    mma_bf16(c[mt][nt], ah[mt], bl[nt]);
                }
        }
        __syncthreads();
    }

    // epilogue
    #pragma unroll
    for (int nt = 0; nt < 4; nt++) {
        const int cloc = wn * 32 + nt * 8 + 2 * tig;
        const int cc   = col0 + cloc;
        float2 bb = *(const float2*)&bias[cc];
        #pragma unroll
        for (int mt = 0; mt < 2; mt++) {
            #pragma unroll
            for (int hi = 0; hi < 2; hi++) {
                const int r = row0 + wm * 32 + mt * 16 + g + 8 * hi;
                float vx = c[mt][nt][2*hi]     + bb.x;
                float vy = c[mt][nt][2*hi + 1] + bb.y;
                if (MODE == 0) { vx *= 0.125f; vy *= 0.125f; }
                if (MODE == 0 || MODE == 1) {
                    const int b = r >> 11;
                    const int s = r & 2047;
                    const size_t wi = ((size_t)(b * HEADS + blockIdx.y) * SEQ + s) * 32
                                      + (cloc >> 1);
                    unsigned hw, lw;
                    split_pack(vx, vy, hw, lw);
                    if (MODE == 0) { ((unsigned*)g_qh)[wi] = hw; ((unsigned*)g_ql)[wi] = lw; }
                    else           { ((unsigned*)g_kh)[wi] = hw; ((unsigned*)g_kl)[wi] = lw; }
                } else if (MODE == 2) {
                    const int b = r >> 11;
                    const int s = r & 2047;
                    const size_t bhh = (size_t)(b * HEADS + blockIdx.y) * HDIM;
                    unsigned short h0, l0, h1, l1;
                    split1(vx, h0, l0);
                    split1(vy, h1, l1);
                    g_vh[(bhh + cloc)     * SEQ + s] = h0;
                    g_vl[(bhh + cloc)     * SEQ + s] = l0;
                    g_vh[(bhh + cloc + 1) * SEQ + s] = h1;
                    g_vl[(bhh + cloc + 1) * SEQ + s] = l1;
                } else {
                    *(float2*)&outp[(size_t)r * DIM + cc] = make_float2(vx, vy);
                }
            }
        }
    }
}

// ---------------------------------------------------------------------------
// Flash attention, split-bf16 mma + ldmatrix fragments.
// ---------------------------------------------------------------------------
__global__ __launch_bounds__(256) void attn_mma()
{
    extern __shared__ __align__(16) unsigned smw[];
    unsigned* Qh = smw;
    unsigned* Ql = Qh + 128*36;
    unsigned* Kh = Ql + 128*36;
    unsigned* Kl = Kh + 64*36;
    unsigned* Vh = Kl + 64*36;
    unsigned* Vl = Vh + 64*36;
    unsigned* Ph = Vl + 64*36;
    unsigned* Pl = Ph + 128*36;
    float* pmax = (float*)(Pl + 128*36);
    float* psum = pmax + 256;

    const int t    = threadIdx.x;
    const int lane = t & 31;
    const int w    = t >> 5;
    const int g    = lane >> 2;
    const int tig  = lane & 3;
    const int wm   = w & 3;
    const int wn   = w >> 2;
    const int qt   = blockIdx.x;
    const int bh   = blockIdx.y;

    const int lj = lane >> 3, lr = lane & 7;
    const int afr = wm * 32 + (lj & 1) * 8 + lr;
    const int afw = (lj >> 1) * 4;
    const int bfn = wn * 32 + (lj >> 1) * 8 + lr;
    const int bfw = (lj & 1) * 4;

    const uint32_t QhB = (uint32_t)__cvta_generic_to_shared(Qh);
    const uint32_t QlB = (uint32_t)__cvta_generic_to_shared(Ql);
    const uint32_t KhB = (uint32_t)__cvta_generic_to_shared(Kh);
    const uint32_t KlB = (uint32_t)__cvta_generic_to_shared(Kl);
    const uint32_t VhB = (uint32_t)__cvta_generic_to_shared(Vh);
    const uint32_t VlB = (uint32_t)__cvta_generic_to_shared(Vl);
    const uint32_t PhB = (uint32_t)__cvta_generic_to_shared(Ph);
    const uint32_t PlB = (uint32_t)__cvta_generic_to_shared(Pl);

    const unsigned* Qgh = (const unsigned*)g_qh + (size_t)bh * SEQ * 32;
    const unsigned* Qgl = (const unsigned*)g_ql + (size_t)bh * SEQ * 32;
    const unsigned* Kgh = (const unsigned*)g_kh + (size_t)bh * SEQ * 32;
    const unsigned* Kgl = (const unsigned*)g_kl + (size_t)bh * SEQ * 32;
    const unsigned* Vgh = (const unsigned*)g_vh + (size_t)bh * HDIM * (SEQ / 2);
    const unsigned* Vgl = (const unsigned*)g_vl + (size_t)bh * HDIM * (SEQ / 2);

    // stage Q
    {
        const int r    = t >> 1;
        const int half = (t & 1) * 16;
        const size_t gi = (size_t)(qt * 128 + r) * 32 + half;
        #pragma unroll
        for (int j = 0; j < 4; j++) {
            *(uint4*)&Qh[r * 36 + half + j * 4] = *(const uint4*)&Qgh[gi + j * 4];
            *(uint4*)&Ql[r * 36 + half + j * 4] = *(const uint4*)&Qgl[gi + j * 4];
        }
    }

    float mst[2][2], lst[2][2], o[2][4][4];
    #pragma unroll
    for (int mt = 0; mt < 2; mt++)
        #pragma unroll
        for (int hi = 0; hi < 2; hi++) { mst[mt][hi] = -1e30f; lst[mt][hi] = 0.f; }
    #pragma unroll
    for (int mt = 0; mt < 2; mt++)
        #pragma unroll
        for (int nt = 0; nt < 4; nt++)
            #pragma unroll
            for (int i = 0; i < 4; i++) o[mt][nt][i] = 0.f;

    const int sr = t >> 2;
    const int sp = (t & 3) * 8;

    for (int kt = 0; kt < SEQ / 64; kt++) {
        __syncthreads();
        {
            const size_t ki = (size_t)(kt * 64 + sr) * 32 + sp;
            *(uint4*)&Kh[sr * 36 + sp]     = *(const uint4*)&Kgh[ki];
            *(uint4*)&Kh[sr * 36 + sp + 4] = *(const uint4*)&Kgh[ki + 4];
            *(uint4*)&Kl[sr * 36 + sp]     = *(const uint4*)&Kgl[ki];
            *(uint4*)&Kl[sr * 36 + sp + 4] = *(const uint4*)&Kgl[ki + 4];
            const size_t vi = (size_t)sr * (SEQ / 2) + kt * 32 + sp;
            *(uint4*)&Vh[sr * 36 + sp]     = *(const uint4*)&Vgh[vi];
            *(uint4*)&Vh[sr * 36 + sp + 4] = *(const uint4*)&Vgh[vi + 4];
            *(uint4*)&Vl[sr * 36 + sp]     = *(const uint4*)&Vgl[vi];
            *(uint4*)&Vl[sr * 36 + sp + 4] = *(const uint4*)&Vgl[vi + 4];
        }
        __syncthreads();

        // S = Q @ K^T
        float s[2][4][4];
        #pragma unroll
        for (int mt = 0; mt < 2; mt++)
            #pragma unroll
            for (int nt = 0; nt < 4; nt++)
                #pragma unroll
                for (int i = 0; i < 4; i++) s[mt][nt][i] = 0.f;

        #pragma unroll
        for (int c2 = 0; c2 < 4; c2++) {
            const int base = c2 * 8;
            unsigned ah[2][4], al[2][4], bhf[4][2], blf[4][2];
            #pragma unroll
            for (int mt = 0; mt < 2; mt++) {
                const uint32_t off = ((afr + mt * 16) * 36 + base + afw) * 4;
                ldsm_x4(ah[mt], QhB + off);
                ldsm_x4(al[mt], QlB + off);
            }
            #pragma unroll
            for (int pr = 0; pr < 2; pr++) {
                const uint32_t off = ((bfn + pr * 16) * 36 + base + bfw) * 4;
                unsigned rh[4], rl[4];
                ldsm_x4(rh, KhB + off);
                ldsm_x4(rl, KlB + off);
                bhf[pr*2][0] = rh[0]; bhf[pr*2][1] = rh[1];
                bhf[pr*2+1][0] = rh[2]; bhf[pr*2+1][1] = rh[3];
                blf[pr*2][0] = rl[0]; blf[pr*2][1] = rl[1];
                blf[pr*2+1][0] = rl[2]; blf[pr*2+1][1] = rl[3];
            }
            #pragma unroll
            for (int mt = 0; mt < 2; mt++)
                #pragma unroll
                for (int nt = 0; nt < 4; nt++) {
                    mma_bf16(s[mt][nt], ah[mt], bhf[nt]);
                    mma_bf16(s[mt][nt], al[mt], bhf[nt]);
                    mma_bf16(s[mt][nt], ah[mt], blf[nt]);
                }
        }

        // online softmax
        #pragma unroll
        for (int mt = 0; mt < 2; mt++)
            #pragma unroll
            for (int hi = 0; hi < 2; hi++) {
                float vm = -1e30f;
                #pragma unroll
                for (int nt = 0; nt < 4; nt++)
                    vm = fmaxf(vm, fmaxf(s[mt][nt][2*hi], s[mt][nt][2*hi+1]));
                vm = fmaxf(vm, __shfl_xor_sync(0xffffffffu, vm, 1));
                vm = fmaxf(vm, __shfl_xor_sync(0xffffffffu, vm, 2));
                if (tig == 0) pmax[(wm*32 + mt*16 + g + 8*hi) * 2 + wn] = vm;
            }
        __syncthreads();

        float f[2][2];
        #pragma unroll
        for (int mt = 0; mt < 2; mt++)
            #pragma unroll
            for (int hi = 0; hi < 2; hi++) {
                const int R = wm*32 + mt*16 + g + 8*hi;
                float gm = fmaxf(pmax[R*2], pmax[R*2 + 1]);
                float mo = mst[mt][hi];
                float mn = fmaxf(mo, gm);
                float ff = __expf(mo - mn);
                f[mt][hi] = ff;
                float rs = 0.f;
                #pragma unroll
                for (int nt = 0; nt < 4; nt++) {
                    float p0 = __expf(s[mt][nt][2*hi]     - mn);
                    float p1 = __expf(s[mt][nt][2*hi + 1] - mn);
                    rs += p0 + p1;
                    unsigned hw, lw;
                    split_pack(p0, p1, hw, lw);
                    const int wi = R * 36 + wn*16 + nt*4 + tig;
                    Ph[wi] = hw;
                    Pl[wi] = lw;
                }
                rs += __shfl_xor_sync(0xffffffffu, rs, 1);
                rs += __shfl_xor_sync(0xffffffffu, rs, 2);
                if (tig == 0) psum[R*2 + wn] = rs;
                mst[mt][hi] = mn;
                #pragma unroll
                for (int nt = 0; nt < 4; nt++) {
                    o[mt][nt][2*hi]     *= ff;
                    o[mt][nt][2*hi + 1] *= ff;
                }
            }
        __syncthreads();
        #pragma unroll
        for (int mt = 0; mt < 2; mt++)
            #pragma unroll
            for (int hi = 0; hi < 2; hi++) {
                const int R = wm*32 + mt*16 + g + 8*hi;
                lst[mt][hi] = lst[mt][hi] * f[mt][hi] + psum[R*2] + psum[R*2 + 1];
            }

        // O += P @ V
        #pragma unroll
        for (int c2 = 0; c2 < 4; c2++) {
            const int base = c2 * 8;
            unsigned ah[2][4], al[2][4], bhf[4][2], blf[4][2];
            #pragma unroll
            for (int mt = 0; mt < 2; mt++) {
                const uint32_t off = ((afr + mt * 16) * 36 + base + afw) * 4;
                ldsm_x4(ah[mt], PhB + off);
                ldsm_x4(al[mt], PlB + off);
            }
            #pragma unroll
            for (int pr = 0; pr < 2; pr++) {
                const uint32_t off = ((bfn + pr * 16) * 36 + base + bfw) * 4;
                unsigned rh[4], rl[4];
                ldsm_x4(rh, VhB + off);
                ldsm_x4(rl, VlB + off);
                bhf[pr*2][0] = rh[0]; bhf[pr*2][1] = rh[1];
                bhf[pr*2+1][0] = rh[2]; bhf[pr*2+1][1] = rh[3];
                blf[pr*2][0] = rl[0]; blf[pr*2][1] = rl[1];
                blf[pr*2+1][0] = rl[2]; blf[pr*2+1][1] = rl[3];
            }
            #pragma unroll
            for (int mt = 0; mt < 2; mt++)
                #pragma unroll
                for (int nt = 0; nt < 4; nt++) {
                    mma_bf16(o[mt][nt], ah[mt], bhf[nt]);
                    mma_bf16(o[mt][nt], al[mt], bhf[nt]);
                    mma_bf16(o[mt][nt], ah[mt], blf[nt]);
                }
        }
    }

    // finalize -> split heads planes
    const int b = bh >> 4, h = bh & 15;
    #pragma unroll
    for (int mt = 0; mt < 2; mt++)
        #pragma unroll
        for (int hi = 0; hi < 2; hi++) {
            const int R = wm*32 + mt*16 + g + 8*hi;
            const float inv = 1.f / lst[mt][hi];
            const size_t grow = (size_t)(b * SEQ + qt * 128 + R);
            #pragma unroll
            for (int nt = 0; nt < 4; nt++) {
                const int cc = wn*32 + nt*8 + 2*tig;
                float vx = o[mt][nt][2*hi]     * inv;
                float vy = o[mt][nt][2*hi + 1] * inv;
                unsigned hw, lw;
                split_pack(vx, vy, hw, lw);
                const size_t wi = grow * (DIM / 2) + ((h * HDIM + cc) >> 1);
                ((unsigned*)g_hh)[wi] = hw;
                ((unsigned*)g_hl)[wi] = lw;
            }
        }
}

#define ATTN_SMEM ((36*(128+128+64+64+64+64+128+128) + 512) * (int)sizeof(unsigned))

extern "C" void kernel_launch(void* const* d_in, const int* in_sizes, int n_in,
                              void* d_out, int out_size)
{
    const float* x  = (const float*)d_in[0];
    const float* bq = (const float*)d_in[2];
    const float* bk = (const float*)d_in[4];
    const float* bv = (const float*)d_in[6];
    const float* bo = (const float*)d_in[8];
    const float* Wq = (const float*)d_in[1];
    const float* Wk = (const float*)d_in[3];
    const float* Wv = (const float*)d_in[5];
    const float* Wo = (const float*)d_in[7];
    float* out = (float*)d_out;

    cudaFuncSetAttribute(attn_mma,
                         cudaFuncAttributeMaxDynamicSharedMemorySize, ATTN_SMEM);

    prep_x<<<(MROWS * DIM / 4) / 256, 256>>>(x);
    prep_w<<<dim3(DIM / 64, DIM / 64, 4), 256>>>(Wq, Wk, Wv, Wo);

    const dim3 pg(MROWS / 128, HEADS);
    proj<0><<<pg, 256>>>(bq, nullptr);
    proj<1><<<pg, 256>>>(bk, nullptr);
    proj<2><<<pg, 256>>>(bv, nullptr);

    attn_mma<<<dim3(SEQ / 128, BATCH * HEADS), 256, ATTN_SMEM>>>();

    proj<3><<<pg, 256>>>(bo, out);
}